// round 15
// baseline (speedup 1.0000x reference)
#include <cuda_runtime.h>
#include <cuda_bf16.h>
#include <cstdint>

#define E_ 8
#define D_ 512
#define P_ 32
#define BMAX 8192
#define MTOK 64
#define THREADS 256
#define FULLM 0xffffffffu

#define ROWB 1040

// ---- smem layout (bytes) ----
#define SM_B     0                       // 32*1040 = 33280; reused as cross[128][36]
#define SM_S2    33280                   // 128 floats
#define SM_P2    33792                   // 32 floats
#define SMEM_BYTES 33920
#define SM_CROSS 0
#define CSTRIDE  36

// ---- persistent scratch ----
__device__ __align__(256) __nv_bfloat16 g_ancBF[(size_t)BMAX * D_];  // anchor rows, bf16
__device__ __align__(256) float g_s2a[BMAX];                         // anchor norms
__device__ int   g_flags[BMAX / MTOK];
__device__ int   g_zero = 0;

static __device__ __forceinline__ uint32_t smem_u32(const void* p) {
    return (uint32_t)__cvta_generic_to_shared(p);
}

#define LDSM_X4(r0, r1, r2, r3, addr) \
    asm volatile("ldmatrix.sync.aligned.m8n8.x4.shared.b16 {%0,%1,%2,%3}, [%4];" \
        : "=r"(r0), "=r"(r1), "=r"(r2), "=r"(r3) : "r"(addr))

static __device__ __forceinline__ void mma16816(float* d, const uint32_t* a,
                                                uint32_t b0, uint32_t b1) {
    asm volatile(
        "mma.sync.aligned.m16n8k16.row.col.f32.bf16.bf16.f32 "
        "{%0,%1,%2,%3}, {%4,%5,%6,%7}, {%8,%9}, {%0,%1,%2,%3};"
        : "+f"(d[0]), "+f"(d[1]), "+f"(d[2]), "+f"(d[3])
        : "r"(a[0]), "r"(a[1]), "r"(a[2]), "r"(a[3]), "r"(b0), "r"(b1));
}

static __device__ __forceinline__ uint32_t packbf(float x, float y) {
    __nv_bfloat162 h = __floats2bfloat162_rn(x, y);
    return *reinterpret_cast<uint32_t*>(&h);
}

static __device__ __forceinline__ float frcp(float x) {
    float y;
    asm("rcp.approx.f32 %0, %1;" : "=f"(y) : "f"(x));
    return y;
}

static __device__ __forceinline__ int ld_acquire(const int* p) {
    int v;
    asm volatile("ld.acquire.gpu.b32 %0, [%1];" : "=r"(v) : "l"(p) : "memory");
    return v;
}

// ---------------- flag reset (runs first, every call) ----------------
__global__ void zero_flags(int n) {
    int i = threadIdx.x;
    if (i < n) g_flags[i] = 0;
}

// ---------------- single fused kernel ----------------
// grid (E_, G): blockIdx.x = e (fastest), blockIdx.y = bb.
//   e == fi : trivial outputs + convert this block's 64 anchor rows to bf16, set flag
//   e != fi : token warps (0-3) fp32 A + cvt inline; anchor warps (4-7) bf16 A after flag
__global__ __launch_bounds__(THREADS, 4)
void otng_hyb(const float* __restrict__ tokens,
              const float* __restrict__ protos,
              const int* __restrict__ fi_ptr,
              float* __restrict__ out, int B) {
    extern __shared__ char smem[];
    const int e    = blockIdx.x;
    const int bb   = blockIdx.y;
    const int b0   = bb * MTOK;
    const int tid  = threadIdx.x;
    const int wid  = tid >> 5;
    const int lane = tid & 31;
    const int fi   = *fi_ptr;
    const int BE   = B * E_;

    if (e == fi) {
        // ---- trivial outputs ----
        if (tid < MTOK) {
            int b = b0 + tid;
            out[b * E_ + e]      = 1.0f;
            out[BE + b * E_ + e] = 0.0f;
        }
        // ---- anchor prep: 64 rows of column fi -> bf16 + norms ----
        #pragma unroll 2
        for (int rr = 0; rr < 8; ++rr) {
            const int r = wid * 8 + rr;                 // 0..63
            const int b = b0 + r;
            const float4* s4 = (const float4*)(tokens + ((size_t)b * E_ + fi) * D_);
            __nv_bfloat16* dst = g_ancBF + (size_t)(b0 + r) * D_;
            float nrm = 0.f;
            #pragma unroll
            for (int j = 0; j < 4; ++j) {
                float4 v = s4[j * 32 + lane];
                nrm = fmaf(v.x, v.x, fmaf(v.y, v.y, fmaf(v.z, v.z, fmaf(v.w, v.w, nrm))));
                uint2 pk;
                pk.x = packbf(v.x, v.y);
                pk.y = packbf(v.z, v.w);
                *reinterpret_cast<uint2*>(dst + j * 128 + lane * 4) = pk;
            }
            #pragma unroll
            for (int o = 16; o; o >>= 1) nrm += __shfl_xor_sync(FULLM, nrm, o);
            if (lane == 0) g_s2a[b0 + r] = nrm;
        }
        __threadfence();
        __syncthreads();
        if (tid == 0) atomicExch(&g_flags[bb], 1);
        return;
    }

    const uint32_t sbase = smem_u32(smem);
    float* s2s = (float*)(smem + SM_S2);
    float* p2s = (float*)(smem + SM_P2);

    // ---- stage B from fp32 protos: superblock k-permutation + p2 norms ----
    // superblock sb holds k in [32sb, 32sb+32); quad slot m owns kk=8m..8m+7:
    // (8m,8m+1)@m*4, (8m+2,8m+3)@16+m*4, (8m+4,8m+5)@32+m*4, (8m+6,8m+7)@48+m*4
    #pragma unroll 1
    for (int k = 0; k < 4; ++k) {
        const int p = wid + k * 8;
        const float* src = protos + ((size_t)e * P_ + p) * D_;
        float nrm = 0.f;
        #pragma unroll
        for (int j = 0; j < 2; ++j) {
            const int c8 = j * 32 + lane;
            float4 va = *(const float4*)(src + 8 * c8);
            float4 vb = *(const float4*)(src + 8 * c8 + 4);
            nrm = fmaf(va.x, va.x, fmaf(va.y, va.y, fmaf(va.z, va.z, fmaf(va.w, va.w, nrm))));
            nrm = fmaf(vb.x, vb.x, fmaf(vb.y, vb.y, fmaf(vb.z, vb.z, fmaf(vb.w, vb.w, nrm))));
            const int bbk = c8 >> 2;
            const int m   = c8 & 3;
            char* base = smem + SM_B + p * ROWB + bbk * 64 + m * 4;
            *reinterpret_cast<uint32_t*>(base)      = packbf(va.x, va.y);
            *reinterpret_cast<uint32_t*>(base + 16) = packbf(va.z, va.w);
            *reinterpret_cast<uint32_t*>(base + 32) = packbf(vb.x, vb.y);
            *reinterpret_cast<uint32_t*>(base + 48) = packbf(vb.z, vb.w);
        }
        #pragma unroll
        for (int o = 16; o; o >>= 1) nrm += __shfl_xor_sync(FULLM, nrm, o);
        if (lane == 0) p2s[p] = nrm;
    }

    // ---- anchor warps wait for this block's prep, then load anchor norms ----
    if (wid >= 4) {
        if (lane == 0) {
            while (ld_acquire(&g_flags[bb]) == 0) __nanosleep(64);
        }
        __syncwarp();
        if (wid == 4) {
            s2s[64 + lane] = g_s2a[b0 + lane];
            s2s[96 + lane] = g_s2a[b0 + 32 + lane];
        }
    }
    __syncthreads();

    // ---- HMMA GEMM (superblock permutation on both operands) ----
    float acc[16];
    #pragma unroll
    for (int i = 0; i < 16; ++i) acc[i] = 0.f;

    const int gr = lane >> 2;
    const int m  = lane & 3;
    const int r0 = wid * 16 + gr;
    const int bn  = (lane & 7) + ((lane >> 4) << 3);
    const int bk  = ((lane >> 3) & 1) * 8;
    const uint32_t bAddr0 = sbase + SM_B + (uint32_t)bn * ROWB + (uint32_t)(bk * 2);
    const uint32_t bAddr1 = bAddr0 + 16u * ROWB;

    if (wid < 4) {
        // ===== token warps: fp32 A + inline cvt + norms =====
        const int bt0 = b0 + r0;
        const float* pA0 = tokens + ((size_t)bt0 * E_ + e) * D_ + 8 * m;
        const float* pA1 = tokens + ((size_t)(bt0 + 8) * E_ + e) * D_ + 8 * m;
        float nrm0 = 0.f, nrm1 = 0.f;

        #pragma unroll 4
        for (int sb = 0; sb < 16; ++sb) {
            float4 xa = *(const float4*)(pA0 + sb * 32);
            float4 xb = *(const float4*)(pA0 + sb * 32 + 4);
            float4 ya = *(const float4*)(pA1 + sb * 32);
            float4 yb = *(const float4*)(pA1 + sb * 32 + 4);
            nrm0 = fmaf(xa.x, xa.x, fmaf(xa.y, xa.y, fmaf(xa.z, xa.z, fmaf(xa.w, xa.w, nrm0))));
            nrm0 = fmaf(xb.x, xb.x, fmaf(xb.y, xb.y, fmaf(xb.z, xb.z, fmaf(xb.w, xb.w, nrm0))));
            nrm1 = fmaf(ya.x, ya.x, fmaf(ya.y, ya.y, fmaf(ya.z, ya.z, fmaf(ya.w, ya.w, nrm1))));
            nrm1 = fmaf(yb.x, yb.x, fmaf(yb.y, yb.y, fmaf(yb.z, yb.z, fmaf(yb.w, yb.w, nrm1))));
            uint32_t a0[4], a1[4];
            a0[0] = packbf(xa.x, xa.y); a0[2] = packbf(xa.z, xa.w);
            a0[1] = packbf(ya.x, ya.y); a0[3] = packbf(ya.z, ya.w);
            a1[0] = packbf(xb.x, xb.y); a1[2] = packbf(xb.z, xb.w);
            a1[1] = packbf(yb.x, yb.y); a1[3] = packbf(yb.z, yb.w);

            uint32_t p0, p1, p2, p3, q0, q1, q2, q3;
            LDSM_X4(p0, p1, p2, p3, bAddr0 + sb * 64);
            LDSM_X4(q0, q1, q2, q3, bAddr1 + sb * 64);
            mma16816(acc + 0,  a0, p0, p1);
            mma16816(acc + 4,  a0, p2, p3);
            mma16816(acc + 8,  a0, q0, q1);
            mma16816(acc + 12, a0, q2, q3);
            LDSM_X4(p0, p1, p2, p3, bAddr0 + sb * 64 + 32);
            LDSM_X4(q0, q1, q2, q3, bAddr1 + sb * 64 + 32);
            mma16816(acc + 0,  a1, p0, p1);
            mma16816(acc + 4,  a1, p2, p3);
            mma16816(acc + 8,  a1, q0, q1);
            mma16816(acc + 12, a1, q2, q3);
        }
        nrm0 += __shfl_xor_sync(FULLM, nrm0, 1);
        nrm0 += __shfl_xor_sync(FULLM, nrm0, 2);
        nrm1 += __shfl_xor_sync(FULLM, nrm1, 1);
        nrm1 += __shfl_xor_sync(FULLM, nrm1, 2);
        if (m == 0) { s2s[r0] = nrm0; s2s[r0 + 8] = nrm1; }
    } else {
        // ===== anchor warps: bf16 A direct (L2-hot), no cvt/norms =====
        const int ar0 = r0 - 64;                       // 0..63
        const __nv_bfloat16* pA0 = g_ancBF + (size_t)(b0 + ar0) * D_ + 8 * m;
        const __nv_bfloat16* pA1 = g_ancBF + (size_t)(b0 + ar0 + 8) * D_ + 8 * m;

        #pragma unroll 4
        for (int sb = 0; sb < 16; ++sb) {
            uint4 u0 = *reinterpret_cast<const uint4*>(pA0 + sb * 32);
            uint4 u1 = *reinterpret_cast<const uint4*>(pA1 + sb * 32);
            uint32_t a0[4], a1[4];
            a0[0] = u0.x; a0[1] = u1.x; a0[2] = u0.y; a0[3] = u1.y;
            a1[0] = u0.z; a1[1] = u1.z; a1[2] = u0.w; a1[3] = u1.w;

            uint32_t p0, p1, p2, p3, q0, q1, q2, q3;
            LDSM_X4(p0, p1, p2, p3, bAddr0 + sb * 64);
            LDSM_X4(q0, q1, q2, q3, bAddr1 + sb * 64);
            mma16816(acc + 0,  a0, p0, p1);
            mma16816(acc + 4,  a0, p2, p3);
            mma16816(acc + 8,  a0, q0, q1);
            mma16816(acc + 12, a0, q2, q3);
            LDSM_X4(p0, p1, p2, p3, bAddr0 + sb * 64 + 32);
            LDSM_X4(q0, q1, q2, q3, bAddr1 + sb * 64 + 32);
            mma16816(acc + 0,  a1, p0, p1);
            mma16816(acc + 4,  a1, p2, p3);
            mma16816(acc + 8,  a1, q0, q1);
            mma16816(acc + 12, a1, q2, q3);
        }
    }
    __syncthreads();   // all ldsm reads of B done -> safe to overwrite with cross

    // ---- scatter accumulators to cross[128][36] (reuses B region) ----
    float* crossS = (float*)(smem + SM_CROSS);
    {
        const int rr0 = wid * 16 + (lane >> 2);
        const int c0  = 2 * (lane & 3);
        #pragma unroll
        for (int nt = 0; nt < 4; ++nt) {
            const int col = nt * 8 + c0;
            *(float2*)(crossS + (size_t)rr0 * CSTRIDE + col)       = make_float2(acc[nt*4+0], acc[nt*4+1]);
            *(float2*)(crossS + (size_t)(rr0 + 8) * CSTRIDE + col) = make_float2(acc[nt*4+2], acc[nt*4+3]);
        }
    }
    __syncthreads();

    // ---- epilogue: quad = one token; Newton on S(r)=sum 1/(1+cp r)=16 ----
    {
        const int T  = tid >> 2;
        const int pl = (tid & 3) * 8;
        const float s2t = s2s[T];
        const float s2a = s2s[64 + T];

        float4 ct0 = *(const float4*)(crossS + (size_t)T * CSTRIDE + pl);
        float4 ct1 = *(const float4*)(crossS + (size_t)T * CSTRIDE + pl + 4);
        float4 ca0 = *(const float4*)(crossS + (size_t)(64 + T) * CSTRIDE + pl);
        float4 ca1 = *(const float4*)(crossS + (size_t)(64 + T) * CSTRIDE + pl + 4);
        float4 pv0 = *(const float4*)(p2s + pl);
        float4 pv1 = *(const float4*)(p2s + pl + 4);

        float ctv[8] = {ct0.x, ct0.y, ct0.z, ct0.w, ct1.x, ct1.y, ct1.z, ct1.w};
        float cav[8] = {ca0.x, ca0.y, ca0.z, ca0.w, ca1.x, ca1.y, ca1.z, ca1.w};
        float pvv[8] = {pv0.x, pv0.y, pv0.z, pv0.w, pv1.x, pv1.y, pv1.z, pv1.w};

        float cp[8], d01[8], sc1 = 0.f;
        #pragma unroll
        for (int j = 0; j < 8; ++j) {
            float c0 = fmaxf(fmaf(-2.f, ctv[j], s2t) + pvv[j], 0.f);
            float c1 = fmaxf(fmaf(-2.f, cav[j], s2a) + pvv[j], 0.f);
            d01[j] = c0 - c1;
            sc1   += c1;
            cp[j]  = __expf(20.f * (c0 - c1));
        }

        float r = 0.f;
        #pragma unroll 1
        for (int it = 0; it < 6; ++it) {
            float f = 0.f, g = 0.f;
            #pragma unroll
            for (int j = 0; j < 8; ++j) {
                float u = frcp(fmaf(cp[j], r, 1.f));
                f += u;
                g = fmaf(cp[j], u * u, g);
            }
            f += __shfl_xor_sync(FULLM, f, 1);
            f += __shfl_xor_sync(FULLM, f, 2);
            g += __shfl_xor_sync(FULLM, g, 1);
            g += __shfl_xor_sync(FULLM, g, 2);
            r = fmaf(f - 16.f, frcp(g), r);
        }

        float ot = sc1;
        #pragma unroll
        for (int j = 0; j < 8; ++j) {
            float w = frcp(fmaf(cp[j], r, 1.f));
            ot = fmaf(w, d01[j], ot);
        }
        ot += __shfl_xor_sync(FULLM, ot, 1);
        ot += __shfl_xor_sync(FULLM, ot, 2);

        if ((tid & 3) == 0) {
            const int b = b0 + T;
            float o_  = ot * (1.f / 32.f);
            float val = frcp(1.f + __expf(6.f * (o_ - 0.25f)));
            out[b * E_ + e]      = val;
            out[BE + b * E_ + e] = o_;
        }
    }
}

// ---------------- launch ----------------
extern "C" void kernel_launch(void* const* d_in, const int* in_sizes, int n_in,
                              void* d_out, int out_size) {
    const float* tokens = (const float*)d_in[0];
    const float* protos = (const float*)d_in[1];
    const int* fi;
    if (n_in >= 3) {
        fi = (const int*)d_in[2];
    } else {
        void* zp = nullptr;
        cudaGetSymbolAddress(&zp, g_zero);
        fi = (const int*)zp;
    }
    float* out = (float*)d_out;
    const int B = in_sizes[0] / (E_ * D_);
    const int G = B / MTOK;

    zero_flags<<<1, 256>>>(G);

    cudaFuncSetAttribute(otng_hyb,
                         cudaFuncAttributeMaxDynamicSharedMemorySize, SMEM_BYTES);
    dim3 grid(E_, G);
    otng_hyb<<<grid, THREADS, SMEM_BYTES>>>(tokens, protos, fi, out, B);
}

// round 16
// speedup vs baseline: 1.6473x; 1.6473x over previous
#include <cuda_runtime.h>
#include <cuda_bf16.h>
#include <cstdint>

#define E_ 8
#define D_ 512
#define P_ 32
#define MTOK 64             // tokens per CTA; M = 128 rows (64 token + 64 anchor)
#define THREADS 256
#define FULLM 0xffffffffu

// padded bf16 row for B tile: 512 + 8 = 520 elems = 1040 B (ldmatrix conflict-free)
#define ROWB 1040

// ---- smem layout (bytes) ----
#define SM_B     0                       // 32*1040 = 33280; reused as cross[128][36] after MMA
#define SM_S2    33280                   // 128 floats
#define SM_P2    33792                   // 32 floats
#define SM_AST   33920                   // A stages: 8 warps * 4 stages * 1024 B = 32768
#define SMEM_BYTES 66688
#define SM_CROSS 0
#define CSTRIDE  36

__device__ int g_zero = 0;

static __device__ __forceinline__ uint32_t smem_u32(const void* p) {
    return (uint32_t)__cvta_generic_to_shared(p);
}

#define LDSM_X4(r0, r1, r2, r3, addr) \
    asm volatile("ldmatrix.sync.aligned.m8n8.x4.shared.b16 {%0,%1,%2,%3}, [%4];" \
        : "=r"(r0), "=r"(r1), "=r"(r2), "=r"(r3) : "r"(addr))

#define CP_ASYNC16(dst, src) \
    asm volatile("cp.async.cg.shared.global [%0], [%1], 16;" :: "r"(dst), "l"(src))
#define CP_COMMIT() asm volatile("cp.async.commit_group;" ::: "memory")
#define CP_WAIT3()  asm volatile("cp.async.wait_group 3;"  ::: "memory")

#define LDS128F(v, addr) \
    asm volatile("ld.shared.v4.f32 {%0,%1,%2,%3}, [%4];" \
        : "=f"((v).x), "=f"((v).y), "=f"((v).z), "=f"((v).w) : "r"(addr))

static __device__ __forceinline__ void mma16816(float* d, const uint32_t* a,
                                                uint32_t b0, uint32_t b1) {
    asm volatile(
        "mma.sync.aligned.m16n8k16.row.col.f32.bf16.bf16.f32 "
        "{%0,%1,%2,%3}, {%4,%5,%6,%7}, {%8,%9}, {%0,%1,%2,%3};"
        : "+f"(d[0]), "+f"(d[1]), "+f"(d[2]), "+f"(d[3])
        : "r"(a[0]), "r"(a[1]), "r"(a[2]), "r"(a[3]), "r"(b0), "r"(b1));
}

static __device__ __forceinline__ uint32_t packbf(float x, float y) {
    __nv_bfloat162 h = __floats2bfloat162_rn(x, y);
    return *reinterpret_cast<uint32_t*>(&h);
}

static __device__ __forceinline__ float frcp(float x) {
    float y;
    asm("rcp.approx.f32 %0, %1;" : "=f"(y) : "f"(x));
    return y;
}

__global__ __launch_bounds__(THREADS, 3)
void otng_pipe(const float* __restrict__ tokens,
               const float* __restrict__ protos,
               const int* __restrict__ fi_ptr,
               float* __restrict__ out, int B) {
    extern __shared__ char smem[];
    const int e    = blockIdx.x;
    const int bb   = blockIdx.y;
    const int b0   = bb * MTOK;
    const int tid  = threadIdx.x;
    const int wid  = tid >> 5;
    const int lane = tid & 31;
    const int fi   = *fi_ptr;
    const int BE   = B * E_;

    if (e == fi) {                        // trivial expert
        if (tid < MTOK) {
            int b = b0 + tid;
            out[b * E_ + e]      = 1.0f;
            out[BE + b * E_ + e] = 0.0f;
        }
        return;
    }

    const uint32_t sbase = smem_u32(smem);
    float* s2s = (float*)(smem + SM_S2);
    float* p2s = (float*)(smem + SM_P2);

    // ---- stage B: 32 prototypes, 16-k-block permutation (R8-validated) ----
    // frag slots for quad m: {2m,2m+1}->actual{4m,4m+1}, {8+2m,8+2m+1}->{4m+2,4m+3}
    #pragma unroll 1
    for (int k = 0; k < 4; ++k) {
        const int p = wid + k * 8;                    // 0..31
        const float4* src = (const float4*)(protos + ((size_t)e * P_ + p) * D_);
        float nrm = 0.f;
        #pragma unroll
        for (int j = 0; j < 4; ++j) {
            float4 v = src[j * 32 + lane];            // actual k = j*128 + lane*4
            nrm = fmaf(v.x, v.x, fmaf(v.y, v.y, fmaf(v.z, v.z, fmaf(v.w, v.w, nrm))));
            const uint32_t blk = (uint32_t)(j * 8 + (lane >> 2));
            const uint32_t q   = (uint32_t)(lane & 3);
            const uint32_t base = (uint32_t)(p * ROWB) + blk * 32u + q * 4u;
            *reinterpret_cast<uint32_t*>(smem + SM_B + base)      = packbf(v.x, v.y);
            *reinterpret_cast<uint32_t*>(smem + SM_B + base + 16) = packbf(v.z, v.w);
        }
        #pragma unroll
        for (int o = 16; o; o >>= 1) nrm += __shfl_xor_sync(FULLM, nrm, o);
        if (lane == 0) p2s[p] = nrm;
    }
    __syncthreads();

    // ---- HMMA GEMM with cp.async depth-4 A pipeline ----
    float acc[16];
    #pragma unroll
    for (int i = 0; i < 16; ++i) acc[i] = 0.f;
    float nrm0 = 0.f, nrm1 = 0.f;
    {
        const int gr  = lane >> 2;
        const int m   = lane & 3;
        const int r0  = wid * 16 + gr;
        const int col = (wid < 4) ? e : fi;
        const int rBase = b0 + ((wid * 16) & 63);

        // producer lane mapping: lane copies (row=lane>>2, kq=lane&3) and row+8
        const float* src0 = tokens + ((size_t)(rBase + (lane >> 2)) * E_ + col) * D_
                          + (lane & 3) * 4;
        const float* src1 = src0 + (size_t)8 * E_ * D_;
        const uint32_t stBase = sbase + SM_AST + (uint32_t)wid * 4096u;
        const uint32_t dst0 = stBase + (uint32_t)lane * 16u;     // + stage*1024
        const uint32_t dst1 = dst0 + 512u;
        const uint32_t rd0  = stBase + (uint32_t)gr * 64u + (uint32_t)m * 16u;

        const int bn  = (lane & 7) + ((lane >> 4) << 3);
        const int bk  = ((lane >> 3) & 1) * 8;
        const uint32_t bAddr0 = sbase + SM_B + (uint32_t)bn * ROWB + (uint32_t)(bk * 2);
        const uint32_t bAddr1 = bAddr0 + 16u * ROWB;

        // prologue: fill 4 stages
        #pragma unroll
        for (int s = 0; s < 4; ++s) {
            CP_ASYNC16(dst0 + s * 1024u, src0 + s * 16);
            CP_ASYNC16(dst1 + s * 1024u, src1 + s * 16);
            CP_COMMIT();
        }

        #pragma unroll 4
        for (int s = 0; s < 32; ++s) {
            CP_WAIT3();
            __syncwarp();
            const uint32_t sa = rd0 + (uint32_t)(s & 3) * 1024u;
            float4 v0, v1;
            LDS128F(v0, sa);          // row r0,   k = 16s + 4m..4m+3
            LDS128F(v1, sa + 512u);   // row r0+8

            // refill stage (s+4) into slot (s&3) — after the LDS reads above
            if (s < 28) {
                CP_ASYNC16(dst0 + (uint32_t)(s & 3) * 1024u, src0 + (s + 4) * 16);
                CP_ASYNC16(dst1 + (uint32_t)(s & 3) * 1024u, src1 + (s + 4) * 16);
            }
            CP_COMMIT();

            uint32_t a[4];
            a[0] = packbf(v0.x, v0.y); a[2] = packbf(v0.z, v0.w);
            a[1] = packbf(v1.x, v1.y); a[3] = packbf(v1.z, v1.w);
            nrm0 = fmaf(v0.x, v0.x, fmaf(v0.y, v0.y, fmaf(v0.z, v0.z, fmaf(v0.w, v0.w, nrm0))));
            nrm1 = fmaf(v1.x, v1.x, fmaf(v1.y, v1.y, fmaf(v1.z, v1.z, fmaf(v1.w, v1.w, nrm1))));

            uint32_t p0, p1, p2, p3, q0, q1, q2, q3;
            LDSM_X4(p0, p1, p2, p3, bAddr0 + s * 32);
            LDSM_X4(q0, q1, q2, q3, bAddr1 + s * 32);
            mma16816(acc + 0,  a, p0, p1);   // n 0-7
            mma16816(acc + 4,  a, p2, p3);   // n 8-15
            mma16816(acc + 8,  a, q0, q1);   // n 16-23
            mma16816(acc + 12, a, q2, q3);   // n 24-31
        }

        // row norms: reduce across the quad (k pieces)
        nrm0 += __shfl_xor_sync(FULLM, nrm0, 1);
        nrm0 += __shfl_xor_sync(FULLM, nrm0, 2);
        nrm1 += __shfl_xor_sync(FULLM, nrm1, 1);
        nrm1 += __shfl_xor_sync(FULLM, nrm1, 2);
        if (m == 0) { s2s[r0] = nrm0; s2s[r0 + 8] = nrm1; }
    }
    __syncthreads();   // all ldsm reads of B done -> safe to overwrite with cross

    // ---- scatter accumulators to cross[128][36] (reuses B region) ----
    float* crossS = (float*)(smem + SM_CROSS);
    {
        const int rr0 = wid * 16 + (lane >> 2);
        const int c0  = 2 * (lane & 3);
        #pragma unroll
        for (int nt = 0; nt < 4; ++nt) {
            const int col = nt * 8 + c0;
            *(float2*)(crossS + (size_t)rr0 * CSTRIDE + col)       = make_float2(acc[nt*4+0], acc[nt*4+1]);
            *(float2*)(crossS + (size_t)(rr0 + 8) * CSTRIDE + col) = make_float2(acc[nt*4+2], acc[nt*4+3]);
        }
    }
    __syncthreads();

    // ---- epilogue: quad = one token; Newton on S(r)=sum 1/(1+cp r)=16 ----
    {
        const int T  = tid >> 2;
        const int pl = (tid & 3) * 8;
        const float s2t = s2s[T];
        const float s2a = s2s[64 + T];

        float4 ct0 = *(const float4*)(crossS + (size_t)T * CSTRIDE + pl);
        float4 ct1 = *(const float4*)(crossS + (size_t)T * CSTRIDE + pl + 4);
        float4 ca0 = *(const float4*)(crossS + (size_t)(64 + T) * CSTRIDE + pl);
        float4 ca1 = *(const float4*)(crossS + (size_t)(64 + T) * CSTRIDE + pl + 4);
        float4 pv0 = *(const float4*)(p2s + pl);
        float4 pv1 = *(const float4*)(p2s + pl + 4);

        float ctv[8] = {ct0.x, ct0.y, ct0.z, ct0.w, ct1.x, ct1.y, ct1.z, ct1.w};
        float cav[8] = {ca0.x, ca0.y, ca0.z, ca0.w, ca1.x, ca1.y, ca1.z, ca1.w};
        float pvv[8] = {pv0.x, pv0.y, pv0.z, pv0.w, pv1.x, pv1.y, pv1.z, pv1.w};

        float cp[8], d01[8], sc1 = 0.f;
        #pragma unroll
        for (int j = 0; j < 8; ++j) {
            float c0 = fmaxf(fmaf(-2.f, ctv[j], s2t) + pvv[j], 0.f);
            float c1 = fmaxf(fmaf(-2.f, cav[j], s2a) + pvv[j], 0.f);
            d01[j] = c0 - c1;
            sc1   += c1;
            cp[j]  = __expf(20.f * (c0 - c1));        // kb/ka
        }

        float r = 0.f;
        #pragma unroll 1
        for (int it = 0; it < 6; ++it) {
            float f = 0.f, g = 0.f;
            #pragma unroll
            for (int j = 0; j < 8; ++j) {
                float u = frcp(fmaf(cp[j], r, 1.f));
                f += u;
                g = fmaf(cp[j], u * u, g);
            }
            f += __shfl_xor_sync(FULLM, f, 1);
            f += __shfl_xor_sync(FULLM, f, 2);
            g += __shfl_xor_sync(FULLM, g, 1);
            g += __shfl_xor_sync(FULLM, g, 2);
            r = fmaf(f - 16.f, frcp(g), r);
        }

        float ot = sc1;
        #pragma unroll
        for (int j = 0; j < 8; ++j) {
            float w = frcp(fmaf(cp[j], r, 1.f));
            ot = fmaf(w, d01[j], ot);                 // sum_p [w*d01 + c1]
        }
        ot += __shfl_xor_sync(FULLM, ot, 1);
        ot += __shfl_xor_sync(FULLM, ot, 2);

        if ((tid & 3) == 0) {
            const int b = b0 + T;
            float o_  = ot * (1.f / 32.f);
            float val = frcp(1.f + __expf(6.f * (o_ - 0.25f)));
            out[b * E_ + e]      = val;
            out[BE + b * E_ + e] = o_;
        }
    }
}

// ---------------- launch ----------------
extern "C" void kernel_launch(void* const* d_in, const int* in_sizes, int n_in,
                              void* d_out, int out_size) {
    const float* tokens = (const float*)d_in[0];
    const float* protos = (const float*)d_in[1];
    const int* fi;
    if (n_in >= 3) {
        fi = (const int*)d_in[2];
    } else {
        void* zp = nullptr;
        cudaGetSymbolAddress(&zp, g_zero);
        fi = (const int*)zp;
    }
    float* out = (float*)d_out;
    const int B = in_sizes[0] / (E_ * D_);

    cudaFuncSetAttribute(otng_pipe,
                         cudaFuncAttributeMaxDynamicSharedMemorySize, SMEM_BYTES);
    dim3 grid(E_, B / MTOK);
    otng_pipe<<<grid, THREADS, SMEM_BYTES>>>(tokens, protos, fi, out, B);
}